// round 6
// baseline (speedup 1.0000x reference)
#include <cuda_runtime.h>
#include <math.h>

// ---------------------------------------------------------------------------
// Problem constants
// ---------------------------------------------------------------------------
#define T_LEN 512
#define B_SZ  64
#define HID   512
#define G4    2048          // 4*HID (gate rows)
#define CTXD  792
#define INDIM 1048
#define NCTA  128           // persistent recurrence CTAs (4 units each, 1/SM)

// ---------------------------------------------------------------------------
// Device scratch
// ---------------------------------------------------------------------------
__device__ float d_gctx[B_SZ * G4];                               // [b][g]
__device__ float d_P[260 * 8 * G4];                               // [(v*8+j)][g]
__device__ float d_gx0[(size_t)T_LEN * B_SZ * G4];                // [t][b][g]
__device__ float d_gx1[(size_t)T_LEN * B_SZ * G4];                // [t][b][g]
__device__ float d_h1T[(size_t)(T_LEN + 1) * HID * B_SZ];         // [t+1][k][b]
__device__ float d_h2T[(size_t)(T_LEN + 1) * HID * B_SZ];         // [t+1][k][b]

// Hierarchical barrier state. Monotonic counters + mask checks => no resets,
// deterministic under graph replay. Group counters 128B apart (distinct LTS
// lines -> parallel atomic ALUs; single-address serialization was costing
// ~7K cyc/step at 256 arrivals).
__device__ unsigned g_grp[16 * 32];      // 16 counters, stride 32 uints = 128B
__device__ unsigned g_done = 0;
__device__ volatile unsigned g_gen = 0;

// ---------------------------------------------------------------------------
// Software grid barrier for NCTA=128 co-resident CTAs (1/SM).
// Arrivals: 8 CTAs -> group counter (16 groups, parallel), 16 leaders ->
// g_done, last leader bumps g_gen. Spin on g_gen (read-only L2 broadcast).
// ---------------------------------------------------------------------------
__device__ __forceinline__ void grid_sync() {
    __syncthreads();
    if (threadIdx.x == 0) {
        unsigned my = g_gen;                         // read BEFORE arriving
        __threadfence();                             // publish h stores
        bool released = false;
        if ((atomicAdd(&g_grp[(blockIdx.x >> 3) * 32], 1u) & 7u) == 7u) {
            if ((atomicAdd(&g_done, 1u) & 15u) == 15u) {
                __threadfence();
                g_gen = my + 1;                      // release
                released = true;
            }
        }
        if (!released) while (g_gen == my) { }       // volatile spin
    }
    __syncthreads();
}

// ---------------------------------------------------------------------------
// K0: zero the t=0 slabs of both hidden-state buffers.
// ---------------------------------------------------------------------------
__global__ void zero_h0_kernel() {
    int i = blockIdx.x * blockDim.x + threadIdx.x;
    if (i < HID * B_SZ) { d_h1T[i] = 0.f; d_h2T[i] = 0.f; }
}

// ---------------------------------------------------------------------------
// K1: gctx[b][g] = (b_ih0+b_hh0)[g] + ctxvec[b] . W_ih0[g][0:792]
// ---------------------------------------------------------------------------
__global__ __launch_bounds__(256) void gctx_kernel(
    const float* __restrict__ conv,      // [64][512]
    const int*   __restrict__ cat,       // [64][3]
    const float* __restrict__ num,       // [64][16]
    const float* __restrict__ ce0,       // [10][50]
    const float* __restrict__ ce1,       // [128][64]
    const float* __restrict__ ce2,       // [300][150]
    const float* __restrict__ W_ih0,     // [2048][1048]
    const float* __restrict__ b_ih0,
    const float* __restrict__ b_hh0)
{
    __shared__ __align__(16) float ctx[CTXD];
    int b = blockIdx.x, tid = threadIdx.x;
    int i0 = cat[b * 3 + 0], i1 = cat[b * 3 + 1], i2 = cat[b * 3 + 2];
    for (int i = tid; i < 512; i += 256) ctx[i]       = conv[b * 512 + i];
    for (int i = tid; i < 50;  i += 256) ctx[512 + i] = ce0[i0 * 50 + i];
    for (int i = tid; i < 64;  i += 256) ctx[562 + i] = ce1[i1 * 64 + i];
    for (int i = tid; i < 150; i += 256) ctx[626 + i] = ce2[i2 * 150 + i];
    for (int i = tid; i < 16;  i += 256) ctx[776 + i] = num[b * 16 + i];
    __syncthreads();

    const float4* cv = (const float4*)ctx;           // 198 float4s
    for (int g = tid; g < G4; g += 256) {
        const float4* wr = (const float4*)(W_ih0 + (size_t)g * INDIM);
        float acc = b_ih0[g] + b_hh0[g];
        #pragma unroll 4
        for (int kk = 0; kk < 198; ++kk) {
            float4 w = wr[kk], c4 = cv[kk];
            acc = fmaf(w.x, c4.x, fmaf(w.y, c4.y, fmaf(w.z, c4.z, fmaf(w.w, c4.w, acc))));
        }
        d_gctx[b * G4 + g] = acc;
    }
}

// ---------------------------------------------------------------------------
// K2: byte projection table P[(v*8+j)][g] = byte_emb[v] . W_ih0[g][792+32j : +32]
// ---------------------------------------------------------------------------
__global__ __launch_bounds__(256) void ptable_kernel(
    const float* __restrict__ byte_emb,  // [260][32]
    const float* __restrict__ W_ih0)
{
    int pid = blockIdx.x;                // v*8 + j
    int v = pid >> 3, j = pid & 7;
    __shared__ float e[32];
    if (threadIdx.x < 32) e[threadIdx.x] = byte_emb[v * 32 + threadIdx.x];
    __syncthreads();
    for (int g = threadIdx.x; g < G4; g += 256) {
        const float* wr = W_ih0 + (size_t)g * INDIM + CTXD + j * 32;
        float acc = 0.f;
        #pragma unroll
        for (int d = 0; d < 32; ++d) acc = fmaf(e[d], wr[d], acc);
        d_P[(size_t)pid * G4 + g] = acc;
    }
}

// ---------------------------------------------------------------------------
// K3: gx0[t][b][g] = gctx[b][g] + sum_j P[pad(b,t+j)*8+j][g]
// ---------------------------------------------------------------------------
__global__ __launch_bounds__(128) void gx0_kernel(
    const int* __restrict__ payload)     // [64][512]
{
    int t = blockIdx.x, b = blockIdx.y, tid = threadIdx.x;
    __shared__ int rows[8];
    if (tid < 8) {
        int q = t + tid;
        int v = (q < 7) ? 256 : ((q == 7) ? 257 : payload[b * 512 + (q - 8)]);
        rows[tid] = v * 8 + tid;
    }
    __syncthreads();
    float4* outp = (float4*)(d_gx0 + ((size_t)t * B_SZ + b) * G4);
    const float4* gc = (const float4*)(d_gctx + b * G4);
    #pragma unroll
    for (int p = 0; p < 4; ++p) {
        int g4 = p * 128 + tid;          // float4 index, 0..511
        float4 acc = gc[g4];
        #pragma unroll
        for (int j = 0; j < 8; ++j) {
            float4 pv = ((const float4*)(d_P + (size_t)rows[j] * G4))[g4];
            acc.x += pv.x; acc.y += pv.y; acc.z += pv.z; acc.w += pv.w;
        }
        outp[g4] = acc;
    }
}

// ---------------------------------------------------------------------------
// K4/K6: persistent LSTM recurrence. 128 CTAs x 512 threads (1/SM).
// CTA owns 4 hidden units; smem caches its 16 W_hh rows (32 KB).
// Thread (bx = tid&63, rg = (tid>>6)&3 -> unit, kh = tid>>8 -> K-half):
// computes 4 gates for (unit, batch bx) over 256 k (1024 FMA).
// kh=1 publishes partials via smem; kh=0 combines + pointwise + stores h.
// hT layout [t+1][k][b] => lane-coalesced loads AND stores.
// ---------------------------------------------------------------------------
__global__ __launch_bounds__(512, 1) void rec_kernel(
    const float* __restrict__ Whh,       // [2048][512]
    int layer)
{
    const float* gx = layer ? d_gx1 : d_gx0;
    float*       hT = layer ? d_h2T : d_h1T;

    __shared__ __align__(16) float Wsh[16][HID];     // 32 KB
    __shared__ __align__(16) float Red[4][B_SZ][4];  // 4 KB  (kh=1 partials)

    int tid = threadIdx.x;
    int u0 = blockIdx.x * 4;
    for (int idx = tid; idx < 16 * HID; idx += 512) {
        int r = idx >> 9, k = idx & 511;             // r = gate*4 + rg
        Wsh[r][k] = Whh[((size_t)(r >> 2) * HID + u0 + (r & 3)) * HID + k];
    }
    // (first grid_sync's __syncthreads orders Wsh before use)

    int bx = tid & 63;
    int rg = (tid >> 6) & 3;
    int kh = tid >> 8;
    int unit = u0 + rg;
    int k0 = kh << 8;                                // 0 or 256

    const float4* w0 = (const float4*)&Wsh[0  + rg][k0];
    const float4* w1 = (const float4*)&Wsh[4  + rg][k0];
    const float4* w2 = (const float4*)&Wsh[8  + rg][k0];
    const float4* w3 = (const float4*)&Wsh[12 + rg][k0];
    float c = 0.f;

    for (int t = 0; t < T_LEN; ++t) {
        grid_sync();                                 // h[t] fully published
        const float* hp = hT + (size_t)t * (HID * B_SZ) + k0 * 64 + bx;

        // prefetch gate inputs (consumed only at loop end; latency hides
        // under the FMA loop)
        float q0 = 0.f, q1 = 0.f, q2 = 0.f, q3 = 0.f;
        if (kh == 0) {
            const float* gxr = gx + ((size_t)t * B_SZ + bx) * G4 + unit;
            q0 = gxr[0]; q1 = gxr[512]; q2 = gxr[1024]; q3 = gxr[1536];
        }

        float a0 = 0.f, a1 = 0.f, a2 = 0.f, a3 = 0.f;
        #pragma unroll 4
        for (int k4 = 0; k4 < 64; ++k4) {
            float4 W0 = w0[k4], W1 = w1[k4], W2 = w2[k4], W3 = w3[k4];
            float h0 = hp[(k4 * 4 + 0) * 64];
            float h1 = hp[(k4 * 4 + 1) * 64];
            float h2 = hp[(k4 * 4 + 2) * 64];
            float h3 = hp[(k4 * 4 + 3) * 64];
            a0 = fmaf(h0, W0.x, a0); a0 = fmaf(h1, W0.y, a0);
            a0 = fmaf(h2, W0.z, a0); a0 = fmaf(h3, W0.w, a0);
            a1 = fmaf(h0, W1.x, a1); a1 = fmaf(h1, W1.y, a1);
            a1 = fmaf(h2, W1.z, a1); a1 = fmaf(h3, W1.w, a1);
            a2 = fmaf(h0, W2.x, a2); a2 = fmaf(h1, W2.y, a2);
            a2 = fmaf(h2, W2.z, a2); a2 = fmaf(h3, W2.w, a2);
            a3 = fmaf(h0, W3.x, a3); a3 = fmaf(h1, W3.y, a3);
            a3 = fmaf(h2, W3.z, a3); a3 = fmaf(h3, W3.w, a3);
        }

        if (kh == 1)
            *(float4*)&Red[rg][bx][0] = make_float4(a0, a1, a2, a3);
        __syncthreads();
        if (kh == 0) {
            float4 p = *(const float4*)&Red[rg][bx][0];
            float gi = a0 + p.x + q0;
            float gf = a1 + p.y + q1;
            float gg = a2 + p.z + q2;
            float go = a3 + p.w + q3;
            float si = 1.f / (1.f + __expf(-gi));
            float sf = 1.f / (1.f + __expf(-gf));
            float so = 1.f / (1.f + __expf(-go));
            c = fmaf(sf, c, si * tanhf(gg));
            hT[(size_t)(t + 1) * (HID * B_SZ) + unit * 64 + bx] = so * tanhf(c);
        }
    }
}

// ---------------------------------------------------------------------------
// K5: gx1[t][b][n] = h1[t][:][b] . W_ih1[n][:] + (b_ih1+b_hh1)[n]
// Tiled fp32 GEMM: block = (n-tile 64, t), M=64 (all b), K=512 in chunks of 16.
// ---------------------------------------------------------------------------
__global__ __launch_bounds__(256) void gemm_gx1_kernel(
    const float* __restrict__ W,         // W_ih1 [2048][512]
    const float* __restrict__ bi,
    const float* __restrict__ bh)
{
    int n0 = blockIdx.x * 64;
    int t  = blockIdx.y;
    __shared__ __align__(16) float As[16][64];
    __shared__ __align__(16) float Bs[16][68];
    int tid = threadIdx.x;
    int tx = tid & 15, ty = tid >> 4;                // tx->n (coalesced writes)
    int lb = tid & 63, lk = tid >> 6;
    int bk = tid & 15, bn = tid >> 4;
    const float* Ap = d_h1T + (size_t)(t + 1) * (HID * B_SZ);
    float acc[4][4] = {};

    for (int kc = 0; kc < HID; kc += 16) {
        #pragma unroll
        for (int i = 0; i < 4; ++i)
            As[lk + 4 * i][lb] = Ap[(size_t)(kc + lk + 4 * i) * 64 + lb];
        #pragma unroll
        for (int i = 0; i < 4; ++i)
            Bs[bk][bn + 16 * i] = W[(size_t)(n0 + bn + 16 * i) * HID + kc + bk];
        __syncthreads();
        #pragma unroll
        for (int ku = 0; ku < 16; ++ku) {
            float4 av = *(const float4*)&As[ku][ty * 4];
            float4 bv = *(const float4*)&Bs[ku][tx * 4];
            acc[0][0] = fmaf(av.x, bv.x, acc[0][0]); acc[0][1] = fmaf(av.x, bv.y, acc[0][1]);
            acc[0][2] = fmaf(av.x, bv.z, acc[0][2]); acc[0][3] = fmaf(av.x, bv.w, acc[0][3]);
            acc[1][0] = fmaf(av.y, bv.x, acc[1][0]); acc[1][1] = fmaf(av.y, bv.y, acc[1][1]);
            acc[1][2] = fmaf(av.y, bv.z, acc[1][2]); acc[1][3] = fmaf(av.y, bv.w, acc[1][3]);
            acc[2][0] = fmaf(av.z, bv.x, acc[2][0]); acc[2][1] = fmaf(av.z, bv.y, acc[2][1]);
            acc[2][2] = fmaf(av.z, bv.z, acc[2][2]); acc[2][3] = fmaf(av.z, bv.w, acc[2][3]);
            acc[3][0] = fmaf(av.w, bv.x, acc[3][0]); acc[3][1] = fmaf(av.w, bv.y, acc[3][1]);
            acc[3][2] = fmaf(av.w, bv.z, acc[3][2]); acc[3][3] = fmaf(av.w, bv.w, acc[3][3]);
        }
        __syncthreads();
    }
    float bz[4];
    #pragma unroll
    for (int j = 0; j < 4; ++j) bz[j] = bi[n0 + tx * 4 + j] + bh[n0 + tx * 4 + j];
    #pragma unroll
    for (int i = 0; i < 4; ++i) {
        int b = ty * 4 + i;
        float4 st = make_float4(acc[i][0] + bz[0], acc[i][1] + bz[1],
                                acc[i][2] + bz[2], acc[i][3] + bz[3]);
        *(float4*)(d_gx1 + ((size_t)t * B_SZ + b) * G4 + n0 + tx * 4) = st;
    }
}

// ---------------------------------------------------------------------------
// K7: logits[b][t][v] = h2[t][:][b] . W_out[v][:] + b_out[v]
// ---------------------------------------------------------------------------
__global__ __launch_bounds__(256) void logits_kernel(
    const float* __restrict__ W,         // W_out [256][512]
    const float* __restrict__ bo,
    float* __restrict__ out)             // [64][512][256]
{
    int n0 = blockIdx.x * 64;
    int t  = blockIdx.y;
    __shared__ __align__(16) float As[16][64];
    __shared__ __align__(16) float Bs[16][68];
    int tid = threadIdx.x;
    int tx = tid & 15, ty = tid >> 4;
    int lb = tid & 63, lk = tid >> 6;
    int bk = tid & 15, bn = tid >> 4;
    const float* Ap = d_h2T + (size_t)(t + 1) * (HID * B_SZ);
    float acc[4][4] = {};

    for (int kc = 0; kc < HID; kc += 16) {
        #pragma unroll
        for (int i = 0; i < 4; ++i)
            As[lk + 4 * i][lb] = Ap[(size_t)(kc + lk + 4 * i) * 64 + lb];
        #pragma unroll
        for (int i = 0; i < 4; ++i)
            Bs[bk][bn + 16 * i] = W[(size_t)(n0 + bn + 16 * i) * HID + kc + bk];
        __syncthreads();
        #pragma unroll
        for (int ku = 0; ku < 16; ++ku) {
            float4 av = *(const float4*)&As[ku][ty * 4];
            float4 bv = *(const float4*)&Bs[ku][tx * 4];
            acc[0][0] = fmaf(av.x, bv.x, acc[0][0]); acc[0][1] = fmaf(av.x, bv.y, acc[0][1]);
            acc[0][2] = fmaf(av.x, bv.z, acc[0][2]); acc[0][3] = fmaf(av.x, bv.w, acc[0][3]);
            acc[1][0] = fmaf(av.y, bv.x, acc[1][0]); acc[1][1] = fmaf(av.y, bv.y, acc[1][1]);
            acc[1][2] = fmaf(av.y, bv.z, acc[1][2]); acc[1][3] = fmaf(av.y, bv.w, acc[1][3]);
            acc[2][0] = fmaf(av.z, bv.x, acc[2][0]); acc[2][1] = fmaf(av.z, bv.y, acc[2][1]);
            acc[2][2] = fmaf(av.z, bv.z, acc[2][2]); acc[2][3] = fmaf(av.z, bv.w, acc[2][3]);
            acc[3][0] = fmaf(av.w, bv.x, acc[3][0]); acc[3][1] = fmaf(av.w, bv.y, acc[3][1]);
            acc[3][2] = fmaf(av.w, bv.z, acc[3][2]); acc[3][3] = fmaf(av.w, bv.w, acc[3][3]);
        }
        __syncthreads();
    }
    float bz[4];
    #pragma unroll
    for (int j = 0; j < 4; ++j) bz[j] = bo[n0 + tx * 4 + j];
    #pragma unroll
    for (int i = 0; i < 4; ++i) {
        int b = ty * 4 + i;
        float4 st = make_float4(acc[i][0] + bz[0], acc[i][1] + bz[1],
                                acc[i][2] + bz[2], acc[i][3] + bz[3]);
        *(float4*)(out + ((size_t)b * T_LEN + t) * 256 + n0 + tx * 4) = st;
    }
}

// ---------------------------------------------------------------------------
// kernel_launch
// ---------------------------------------------------------------------------
extern "C" void kernel_launch(void* const* d_in, const int* in_sizes, int n_in,
                              void* d_out, int out_size) {
    const float* ecc     = (const float*)d_in[0];   // [64,512]
    const int*   cat     = (const int*)  d_in[1];   // [64,3]
    const float* num     = (const float*)d_in[2];   // [64,16]
    const int*   payload = (const int*)  d_in[3];   // [64,512]
    const float* ce0     = (const float*)d_in[4];
    const float* ce1     = (const float*)d_in[5];
    const float* ce2     = (const float*)d_in[6];
    const float* bemb    = (const float*)d_in[7];
    const float* W_ih0   = (const float*)d_in[8];
    const float* W_hh0   = (const float*)d_in[9];
    const float* b_ih0   = (const float*)d_in[10];
    const float* b_hh0   = (const float*)d_in[11];
    const float* W_ih1   = (const float*)d_in[12];
    const float* W_hh1   = (const float*)d_in[13];
    const float* b_ih1   = (const float*)d_in[14];
    const float* b_hh1   = (const float*)d_in[15];
    const float* W_outp  = (const float*)d_in[16];
    const float* b_outp  = (const float*)d_in[17];
    float* out = (float*)d_out;

    zero_h0_kernel<<<64, 512>>>();
    gctx_kernel<<<64, 256>>>(ecc, cat, num, ce0, ce1, ce2, W_ih0, b_ih0, b_hh0);
    ptable_kernel<<<2080, 256>>>(bemb, W_ih0);
    gx0_kernel<<<dim3(T_LEN, B_SZ), 128>>>(payload);
    rec_kernel<<<NCTA, 512>>>(W_hh0, 0);
    gemm_gx1_kernel<<<dim3(32, T_LEN), 256>>>(W_ih1, b_ih1, b_hh1);
    rec_kernel<<<NCTA, 512>>>(W_hh1, 1);
    logits_kernel<<<dim3(4, T_LEN), 256>>>(W_outp, b_outp, out);
}

// round 7
// speedup vs baseline: 1.3543x; 1.3543x over previous
#include <cuda_runtime.h>
#include <math.h>

// ---------------------------------------------------------------------------
// Problem constants
// ---------------------------------------------------------------------------
#define T_LEN 512
#define B_SZ  64
#define HID   512
#define G4    2048          // 4*HID (gate rows)
#define CTXD  792
#define INDIM 1048
#define NCTA  256           // persistent recurrence CTAs (2 units each, 2/SM)

// ---------------------------------------------------------------------------
// Device scratch
// ---------------------------------------------------------------------------
__device__ float d_gctx[B_SZ * G4];                               // [b][g]
__device__ float d_P[260 * 8 * G4];                               // [(v*8+j)][g]
__device__ float d_gx0[(size_t)T_LEN * B_SZ * G4];                // [t][b][g]
__device__ float d_gx1[(size_t)T_LEN * B_SZ * G4];                // [t][b][g]
__device__ float d_h1T[(size_t)(T_LEN + 1) * HID * B_SZ];         // [t+1][k][b]
__device__ float d_h2T[(size_t)(T_LEN + 1) * HID * B_SZ];         // [t+1][k][b]

__device__ unsigned g_cnt = 0;
__device__ volatile unsigned g_gen = 0;

// ---------------------------------------------------------------------------
// Software grid barrier (R4-proven form; all NCTA CTAs co-resident)
// ---------------------------------------------------------------------------
__device__ __forceinline__ void grid_sync() {
    __syncthreads();
    if (threadIdx.x == 0) {
        __threadfence();
        unsigned my = g_gen;                     // read BEFORE arriving
        if (atomicAdd(&g_cnt, 1u) == NCTA - 1) {
            g_cnt = 0;
            __threadfence();
            g_gen = my + 1;                      // release
        } else {
            while (g_gen == my) { }              // volatile spin (L2)
        }
    }
    __syncthreads();
}

// fast, safe pointwise helpers (fp32, err ~1e-7; clamps avoid inf/NaN paths)
__device__ __forceinline__ float sigm(float x) {
    x = fminf(fmaxf(x, -30.f), 30.f);
    return __fdividef(1.f, 1.f + __expf(-x));
}
__device__ __forceinline__ float tanh_f(float x) {
    x = fminf(fmaxf(x, -15.f), 15.f);
    float e = __expf(-2.f * x);
    return (1.f - e) * __fdividef(1.f, 1.f + e);
}

// ---------------------------------------------------------------------------
// K0: zero the t=0 slabs of both hidden-state buffers.
// ---------------------------------------------------------------------------
__global__ void zero_h0_kernel() {
    int i = blockIdx.x * blockDim.x + threadIdx.x;
    if (i < HID * B_SZ) { d_h1T[i] = 0.f; d_h2T[i] = 0.f; }
}

// ---------------------------------------------------------------------------
// K1: gctx[b][g] = (b_ih0+b_hh0)[g] + ctxvec[b] . W_ih0[g][0:792]
// ---------------------------------------------------------------------------
__global__ __launch_bounds__(256) void gctx_kernel(
    const float* __restrict__ conv,      // [64][512]
    const int*   __restrict__ cat,       // [64][3]
    const float* __restrict__ num,       // [64][16]
    const float* __restrict__ ce0,       // [10][50]
    const float* __restrict__ ce1,       // [128][64]
    const float* __restrict__ ce2,       // [300][150]
    const float* __restrict__ W_ih0,     // [2048][1048]
    const float* __restrict__ b_ih0,
    const float* __restrict__ b_hh0)
{
    __shared__ __align__(16) float ctx[CTXD];
    int b = blockIdx.x, tid = threadIdx.x;
    int i0 = cat[b * 3 + 0], i1 = cat[b * 3 + 1], i2 = cat[b * 3 + 2];
    for (int i = tid; i < 512; i += 256) ctx[i]       = conv[b * 512 + i];
    for (int i = tid; i < 50;  i += 256) ctx[512 + i] = ce0[i0 * 50 + i];
    for (int i = tid; i < 64;  i += 256) ctx[562 + i] = ce1[i1 * 64 + i];
    for (int i = tid; i < 150; i += 256) ctx[626 + i] = ce2[i2 * 150 + i];
    for (int i = tid; i < 16;  i += 256) ctx[776 + i] = num[b * 16 + i];
    __syncthreads();

    const float4* cv = (const float4*)ctx;           // 198 float4s
    for (int g = tid; g < G4; g += 256) {
        const float4* wr = (const float4*)(W_ih0 + (size_t)g * INDIM);
        float acc = b_ih0[g] + b_hh0[g];
        #pragma unroll 4
        for (int kk = 0; kk < 198; ++kk) {
            float4 w = wr[kk], c4 = cv[kk];
            acc = fmaf(w.x, c4.x, fmaf(w.y, c4.y, fmaf(w.z, c4.z, fmaf(w.w, c4.w, acc))));
        }
        d_gctx[b * G4 + g] = acc;
    }
}

// ---------------------------------------------------------------------------
// K2: byte projection table P[(v*8+j)][g] = byte_emb[v] . W_ih0[g][792+32j : +32]
// ---------------------------------------------------------------------------
__global__ __launch_bounds__(256) void ptable_kernel(
    const float* __restrict__ byte_emb,  // [260][32]
    const float* __restrict__ W_ih0)
{
    int pid = blockIdx.x;                // v*8 + j
    int v = pid >> 3, j = pid & 7;
    __shared__ float e[32];
    if (threadIdx.x < 32) e[threadIdx.x] = byte_emb[v * 32 + threadIdx.x];
    __syncthreads();
    for (int g = threadIdx.x; g < G4; g += 256) {
        const float* wr = W_ih0 + (size_t)g * INDIM + CTXD + j * 32;
        float acc = 0.f;
        #pragma unroll
        for (int d = 0; d < 32; ++d) acc = fmaf(e[d], wr[d], acc);
        d_P[(size_t)pid * G4 + g] = acc;
    }
}

// ---------------------------------------------------------------------------
// K3: gx0[t][b][g] = gctx[b][g] + sum_j P[pad(b,t+j)*8+j][g]
// ---------------------------------------------------------------------------
__global__ __launch_bounds__(128) void gx0_kernel(
    const int* __restrict__ payload)     // [64][512]
{
    int t = blockIdx.x, b = blockIdx.y, tid = threadIdx.x;
    __shared__ int rows[8];
    if (tid < 8) {
        int q = t + tid;
        int v = (q < 7) ? 256 : ((q == 7) ? 257 : payload[b * 512 + (q - 8)]);
        rows[tid] = v * 8 + tid;
    }
    __syncthreads();
    float4* outp = (float4*)(d_gx0 + ((size_t)t * B_SZ + b) * G4);
    const float4* gc = (const float4*)(d_gctx + b * G4);
    #pragma unroll
    for (int p = 0; p < 4; ++p) {
        int g4 = p * 128 + tid;          // float4 index, 0..511
        float4 acc = gc[g4];
        #pragma unroll
        for (int j = 0; j < 8; ++j) {
            float4 pv = ((const float4*)(d_P + (size_t)rows[j] * G4))[g4];
            acc.x += pv.x; acc.y += pv.y; acc.z += pv.z; acc.w += pv.w;
        }
        outp[g4] = acc;
    }
}

// ---------------------------------------------------------------------------
// K4/K6: persistent LSTM recurrence, software-pipelined.
// 256 CTAs x 256 threads (2/SM). CTA owns 2 hidden units.
// Thread (p = tid&31 -> batch pair (2p,2p+1), rg = (tid>>5)&1 -> unit,
// ks = tid>>6 -> K-quarter of 128 k). Per k: 1 coalesced LDG.64 (h pair) +
// 1 broadcast LDS.128 (4 gate weights) + 8 scalar FMA.
// The h loads for chunk i+1 (16 float2) are issued while chunk i's FMAs run,
// keeping ~4KB/warp in flight -> memory streams at FMA pace instead of
// serializing (the R4-R6 kernels executed mem-burst THEN fma each step).
// K-split partials combined via smem; ks==0 does pointwise for 2 batches.
// ---------------------------------------------------------------------------
__global__ __launch_bounds__(256, 2) void rec_kernel(
    const float* __restrict__ Whh,       // [2048][512]
    int layer)
{
    const float* gx = layer ? d_gx1 : d_gx0;
    float*       hT = layer ? d_h2T : d_h1T;

    __shared__ __align__(16) float Wk[HID][2][4];     // [k][unit][gate] 16 KB
    __shared__ __align__(16) float Red[3][2][32][8];  // [ks-1][unit][pair][2b*4g] 6 KB

    int tid = threadIdx.x;
    int u0 = blockIdx.x * 2;
    for (int idx = tid; idx < HID * 8; idx += 256) {
        int k = idx >> 3, rg_ = (idx >> 2) & 1, g = idx & 3;
        Wk[k][rg_][g] = Whh[((size_t)g * HID + u0 + rg_) * HID + k];
    }
    // (first grid_sync's __syncthreads orders Wk before use)

    int p  = tid & 31;          // batch pair index: b = 2p, 2p+1
    int rg = (tid >> 5) & 1;    // unit within CTA (uniform per warp)
    int ks = tid >> 6;          // K quarter (uniform per warp)
    int unit = u0 + rg;
    int kbase = ks * 128;

    float c0 = 0.f, c1 = 0.f;   // cell states for the 2 batches

#define REC_CHUNK(CH)                                                         \
    _Pragma("unroll")                                                         \
    for (int j = 0; j < 16; ++j) {                                            \
        float4 w = *(const float4*)&Wk[kbase + (CH) * 16 + j][rg][0];         \
        float2 hv = hb[j];                                                    \
        aI0 = fmaf(hv.x, w.x, aI0); aI1 = fmaf(hv.y, w.x, aI1);               \
        aF0 = fmaf(hv.x, w.y, aF0); aF1 = fmaf(hv.y, w.y, aF1);               \
        aG0 = fmaf(hv.x, w.z, aG0); aG1 = fmaf(hv.y, w.z, aG1);               \
        aO0 = fmaf(hv.x, w.w, aO0); aO1 = fmaf(hv.y, w.w, aO1);               \
    }

    for (int t = 0; t < T_LEN; ++t) {
        grid_sync();                                 // h[t] fully published
        const float2* hp2 =
            (const float2*)(hT + (size_t)t * (HID * B_SZ) + (size_t)kbase * 64) + p;

        // gate-input prefetch (consumed only at loop end)
        float q[8];
        if (ks == 0) {
            const float* g0 = gx + ((size_t)t * B_SZ + 2 * p) * G4 + unit;
            #pragma unroll
            for (int g = 0; g < 4; ++g) { q[g] = g0[g * 512]; q[4 + g] = g0[G4 + g * 512]; }
        }

        float aI0=0.f,aF0=0.f,aG0=0.f,aO0=0.f, aI1=0.f,aF1=0.f,aG1=0.f,aO1=0.f;

        float2 hb[16];
        #pragma unroll
        for (int j = 0; j < 16; ++j) hb[j] = hp2[j * 32];     // chunk 0

        #pragma unroll
        for (int ch = 0; ch < 7; ++ch) {
            float2 hn[16];
            #pragma unroll
            for (int j = 0; j < 16; ++j) hn[j] = hp2[((ch + 1) * 16 + j) * 32];
            REC_CHUNK(ch)
            #pragma unroll
            for (int j = 0; j < 16; ++j) hb[j] = hn[j];
        }
        REC_CHUNK(7)

        if (ks != 0) {
            float* r = &Red[ks - 1][rg][p][0];
            *(float4*)r       = make_float4(aI0, aF0, aG0, aO0);
            *(float4*)(r + 4) = make_float4(aI1, aF1, aG1, aO1);
        }
        __syncthreads();
        if (ks == 0) {
            #pragma unroll
            for (int s = 0; s < 3; ++s) {
                const float* r = &Red[s][rg][p][0];
                aI0 += r[0]; aF0 += r[1]; aG0 += r[2]; aO0 += r[3];
                aI1 += r[4]; aF1 += r[5]; aG1 += r[6]; aO1 += r[7];
            }
            float gi0 = aI0 + q[0], gf0 = aF0 + q[1], gg0 = aG0 + q[2], go0 = aO0 + q[3];
            float gi1 = aI1 + q[4], gf1 = aF1 + q[5], gg1 = aG1 + q[6], go1 = aO1 + q[7];
            c0 = fmaf(sigm(gf0), c0, sigm(gi0) * tanh_f(gg0));
            c1 = fmaf(sigm(gf1), c1, sigm(gi1) * tanh_f(gg1));
            float2 hout = make_float2(sigm(go0) * tanh_f(c0), sigm(go1) * tanh_f(c1));
            *((float2*)(hT + (size_t)(t + 1) * (HID * B_SZ) + (size_t)unit * 64) + p) = hout;
        }
    }
#undef REC_CHUNK
}

// ---------------------------------------------------------------------------
// K5: gx1[t][b][n] = h1[t][:][b] . W_ih1[n][:] + (b_ih1+b_hh1)[n]
// ---------------------------------------------------------------------------
__global__ __launch_bounds__(256) void gemm_gx1_kernel(
    const float* __restrict__ W,         // W_ih1 [2048][512]
    const float* __restrict__ bi,
    const float* __restrict__ bh)
{
    int n0 = blockIdx.x * 64;
    int t  = blockIdx.y;
    __shared__ __align__(16) float As[16][64];
    __shared__ __align__(16) float Bs[16][68];
    int tid = threadIdx.x;
    int tx = tid & 15, ty = tid >> 4;                // tx->n (coalesced writes)
    int lb = tid & 63, lk = tid >> 6;
    int bk = tid & 15, bn = tid >> 4;
    const float* Ap = d_h1T + (size_t)(t + 1) * (HID * B_SZ);
    float acc[4][4] = {};

    for (int kc = 0; kc < HID; kc += 16) {
        #pragma unroll
        for (int i = 0; i < 4; ++i)
            As[lk + 4 * i][lb] = Ap[(size_t)(kc + lk + 4 * i) * 64 + lb];
        #pragma unroll
        for (int i = 0; i < 4; ++i)
            Bs[bk][bn + 16 * i] = W[(size_t)(n0 + bn + 16 * i) * HID + kc + bk];
        __syncthreads();
        #pragma unroll
        for (int ku = 0; ku < 16; ++ku) {
            float4 av = *(const float4*)&As[ku][ty * 4];
            float4 bv = *(const float4*)&Bs[ku][tx * 4];
            acc[0][0] = fmaf(av.x, bv.x, acc[0][0]); acc[0][1] = fmaf(av.x, bv.y, acc[0][1]);
            acc[0][2] = fmaf(av.x, bv.z, acc[0][2]); acc[0][3] = fmaf(av.x, bv.w, acc[0][3]);
            acc[1][0] = fmaf(av.y, bv.x, acc[1][0]); acc[1][1] = fmaf(av.y, bv.y, acc[1][1]);
            acc[1][2] = fmaf(av.y, bv.z, acc[1][2]); acc[1][3] = fmaf(av.y, bv.w, acc[1][3]);
            acc[2][0] = fmaf(av.z, bv.x, acc[2][0]); acc[2][1] = fmaf(av.z, bv.y, acc[2][1]);
            acc[2][2] = fmaf(av.z, bv.z, acc[2][2]); acc[2][3] = fmaf(av.z, bv.w, acc[2][3]);
            acc[3][0] = fmaf(av.w, bv.x, acc[3][0]); acc[3][1] = fmaf(av.w, bv.y, acc[3][1]);
            acc[3][2] = fmaf(av.w, bv.z, acc[3][2]); acc[3][3] = fmaf(av.w, bv.w, acc[3][3]);
        }
        __syncthreads();
    }
    float bz[4];
    #pragma unroll
    for (int j = 0; j < 4; ++j) bz[j] = bi[n0 + tx * 4 + j] + bh[n0 + tx * 4 + j];
    #pragma unroll
    for (int i = 0; i < 4; ++i) {
        int b = ty * 4 + i;
        float4 st = make_float4(acc[i][0] + bz[0], acc[i][1] + bz[1],
                                acc[i][2] + bz[2], acc[i][3] + bz[3]);
        *(float4*)(d_gx1 + ((size_t)t * B_SZ + b) * G4 + n0 + tx * 4) = st;
    }
}

// ---------------------------------------------------------------------------
// K7: logits[b][t][v] = h2[t][:][b] . W_out[v][:] + b_out[v]
// ---------------------------------------------------------------------------
__global__ __launch_bounds__(256) void logits_kernel(
    const float* __restrict__ W,         // W_out [256][512]
    const float* __restrict__ bo,
    float* __restrict__ out)             // [64][512][256]
{
    int n0 = blockIdx.x * 64;
    int t  = blockIdx.y;
    __shared__ __align__(16) float As[16][64];
    __shared__ __align__(16) float Bs[16][68];
    int tid = threadIdx.x;
    int tx = tid & 15, ty = tid >> 4;
    int lb = tid & 63, lk = tid >> 6;
    int bk = tid & 15, bn = tid >> 4;
    const float* Ap = d_h2T + (size_t)(t + 1) * (HID * B_SZ);
    float acc[4][4] = {};

    for (int kc = 0; kc < HID; kc += 16) {
        #pragma unroll
        for (int i = 0; i < 4; ++i)
            As[lk + 4 * i][lb] = Ap[(size_t)(kc + lk + 4 * i) * 64 + lb];
        #pragma unroll
        for (int i = 0; i < 4; ++i)
            Bs[bk][bn + 16 * i] = W[(size_t)(n0 + bn + 16 * i) * HID + kc + bk];
        __syncthreads();
        #pragma unroll
        for (int ku = 0; ku < 16; ++ku) {
            float4 av = *(const float4*)&As[ku][ty * 4];
            float4 bv = *(const float4*)&Bs[ku][tx * 4];
            acc[0][0] = fmaf(av.x, bv.x, acc[0][0]); acc[0][1] = fmaf(av.x, bv.y, acc[0][1]);
            acc[0][2] = fmaf(av.x, bv.z, acc[0][2]); acc[0][3] = fmaf(av.x, bv.w, acc[0][3]);
            acc[1][0] = fmaf(av.y, bv.x, acc[1][0]); acc[1][1] = fmaf(av.y, bv.y, acc[1][1]);
            acc[1][2] = fmaf(av.y, bv.z, acc[1][2]); acc[1][3] = fmaf(av.y, bv.w, acc[1][3]);
            acc[2][0] = fmaf(av.z, bv.x, acc[2][0]); acc[2][1] = fmaf(av.z, bv.y, acc[2][1]);
            acc[2][2] = fmaf(av.z, bv.z, acc[2][2]); acc[2][3] = fmaf(av.z, bv.w, acc[2][3]);
            acc[3][0] = fmaf(av.w, bv.x, acc[3][0]); acc[3][1] = fmaf(av.w, bv.y, acc[3][1]);
            acc[3][2] = fmaf(av.w, bv.z, acc[3][2]); acc[3][3] = fmaf(av.w, bv.w, acc[3][3]);
        }
        __syncthreads();
    }
    float bz[4];
    #pragma unroll
    for (int j = 0; j < 4; ++j) bz[j] = bo[n0 + tx * 4 + j];
    #pragma unroll
    for (int i = 0; i < 4; ++i) {
        int b = ty * 4 + i;
        float4 st = make_float4(acc[i][0] + bz[0], acc[i][1] + bz[1],
                                acc[i][2] + bz[2], acc[i][3] + bz[3]);
        *(float4*)(out + ((size_t)b * T_LEN + t) * 256 + n0 + tx * 4) = st;
    }
}

// ---------------------------------------------------------------------------
// kernel_launch
// ---------------------------------------------------------------------------
extern "C" void kernel_launch(void* const* d_in, const int* in_sizes, int n_in,
                              void* d_out, int out_size) {
    const float* ecc     = (const float*)d_in[0];   // [64,512]
    const int*   cat     = (const int*)  d_in[1];   // [64,3]
    const float* num     = (const float*)d_in[2];   // [64,16]
    const int*   payload = (const int*)  d_in[3];   // [64,512]
    const float* ce0     = (const float*)d_in[4];
    const float* ce1     = (const float*)d_in[5];
    const float* ce2     = (const float*)d_in[6];
    const float* bemb    = (const float*)d_in[7];
    const float* W_ih0   = (const float*)d_in[8];
    const float* W_hh0   = (const float*)d_in[9];
    const float* b_ih0   = (const float*)d_in[10];
    const float* b_hh0   = (const float*)d_in[11];
    const float* W_ih1   = (const float*)d_in[12];
    const float* W_hh1   = (const float*)d_in[13];
    const float* b_ih1   = (const float*)d_in[14];
    const float* b_hh1   = (const float*)d_in[15];
    const float* W_outp  = (const float*)d_in[16];
    const float* b_outp  = (const float*)d_in[17];
    float* out = (float*)d_out;

    zero_h0_kernel<<<64, 512>>>();
    gctx_kernel<<<64, 256>>>(ecc, cat, num, ce0, ce1, ce2, W_ih0, b_ih0, b_hh0);
    ptable_kernel<<<2080, 256>>>(bemb, W_ih0);
    gx0_kernel<<<dim3(T_LEN, B_SZ), 128>>>(payload);
    rec_kernel<<<NCTA, 256>>>(W_hh0, 0);
    gemm_gx1_kernel<<<dim3(32, T_LEN), 256>>>(W_ih1, b_ih1, b_hh1);
    rec_kernel<<<NCTA, 256>>>(W_hh1, 1);
    logits_kernel<<<dim3(4, T_LEN), 256>>>(W_outp, b_outp, out);
}